// round 1
// baseline (speedup 1.0000x reference)
#include <cuda_runtime.h>
#include <math.h>

#define B_  4
#define L_  2048
#define H_  12
#define HD_ 64
#define DM_ 768
#define M_  (B_*L_)   // 8192

// Scratch (allocation-free rule: __device__ globals)
__device__ float g_q[B_*H_*L_*HD_];
__device__ float g_k[B_*H_*L_*HD_];
__device__ float g_v[B_*H_*L_*HD_];
__device__ float g_o[M_*DM_];

// ---------------- SGEMM: C[m,n] = sum_k A[m,k]*W[n,k] + bias[n] ----------------
#define BM 128
#define BN 128
#define BK 8

template<bool SCATTER>
__device__ __forceinline__ void gemm_body(const float* __restrict__ A,
                                          const float* __restrict__ W,
                                          const float* __restrict__ bias,
                                          float* __restrict__ C)
{
    __shared__ float As[BK][BM];
    __shared__ float Bs[BK][BN];
    const int bm  = blockIdx.y * BM;
    const int bn  = blockIdx.x * BN;
    const int tid = threadIdx.x;          // 0..255
    const int arow = tid >> 1;            // 0..127
    const int acol = (tid & 1) * 4;       // 0 or 4
    const int tr = tid >> 4;              // 0..15
    const int tc = tid & 15;              // 0..15

    float acc[8][8];
    #pragma unroll
    for (int i = 0; i < 8; i++)
        #pragma unroll
        for (int j = 0; j < 8; j++) acc[i][j] = 0.f;

    const float* Aptr = A + (size_t)(bm + arow) * DM_ + acol;
    const float* Wptr = W + (size_t)(bn + arow) * DM_ + acol;

    for (int k0 = 0; k0 < DM_; k0 += BK) {
        float4 av = *(const float4*)(Aptr + k0);
        float4 wv = *(const float4*)(Wptr + k0);
        As[acol+0][arow] = av.x; As[acol+1][arow] = av.y;
        As[acol+2][arow] = av.z; As[acol+3][arow] = av.w;
        Bs[acol+0][arow] = wv.x; Bs[acol+1][arow] = wv.y;
        Bs[acol+2][arow] = wv.z; Bs[acol+3][arow] = wv.w;
        __syncthreads();
        #pragma unroll
        for (int kk = 0; kk < BK; kk++) {
            float a[8], b[8];
            *(float4*)&a[0] = *(const float4*)&As[kk][tr*8];
            *(float4*)&a[4] = *(const float4*)&As[kk][tr*8 + 4];
            *(float4*)&b[0] = *(const float4*)&Bs[kk][tc*8];
            *(float4*)&b[4] = *(const float4*)&Bs[kk][tc*8 + 4];
            #pragma unroll
            for (int i = 0; i < 8; i++)
                #pragma unroll
                for (int j = 0; j < 8; j++)
                    acc[i][j] += a[i] * b[j];
        }
        __syncthreads();
    }

    #pragma unroll
    for (int i = 0; i < 8; i++) {
        const int m  = bm + tr*8 + i;
        const int bb = m / L_;
        const int l  = m % L_;
        #pragma unroll
        for (int j = 0; j < 8; j++) {
            const int n = bn + tc*8 + j;
            const float v = acc[i][j] + bias[n];
            if (SCATTER) {
                const int h = n / HD_;
                const int d = n % HD_;
                C[(((size_t)bb*H_ + h)*L_ + l)*HD_ + d] = v;
            } else {
                C[(size_t)m*DM_ + n] = v;
            }
        }
    }
}

__global__ __launch_bounds__(256) void qkv_gemm(const float* __restrict__ X,
    const float* __restrict__ wq, const float* __restrict__ bq,
    const float* __restrict__ wk, const float* __restrict__ bk,
    const float* __restrict__ wv, const float* __restrict__ bv)
{
    const float* W; const float* bias; float* out;
    if (blockIdx.z == 0)      { W = wq; bias = bq; out = g_q; }
    else if (blockIdx.z == 1) { W = wk; bias = bk; out = g_k; }
    else                      { W = wv; bias = bv; out = g_v; }
    gemm_body<true>(X, W, bias, out);
}

__global__ __launch_bounds__(256) void out_gemm(const float* __restrict__ wo,
                                                const float* __restrict__ bo,
                                                float* __restrict__ out)
{
    gemm_body<false>(g_o, wo, bo, out);
}

// ---------------- Causal flash attention ----------------
// Q,K,V: [B,H,L,HD]; O written as [B,L,H,HD] (= [B,L,DM] row-major)
#define FBM 128
#define FBN 64

__global__ __launch_bounds__(128) void flash_kernel()
{
    extern __shared__ float sm[];
    float* Ks = sm;                       // FBN*HD
    float* Vs = sm + FBN*HD_;             // FBN*HD
    float* Ss = sm + 2*FBN*HD_;           // FBM * 65 (padded rows)

    const int tid = threadIdx.x;          // query row within tile, 0..127
    const int qt = blockIdx.x;
    const int h  = blockIdx.y;
    const int b  = blockIdx.z;

    const float* Qb = g_q + (size_t)(b*H_ + h) * L_ * HD_;
    const float* Kb = g_k + (size_t)(b*H_ + h) * L_ * HD_;
    const float* Vb = g_v + (size_t)(b*H_ + h) * L_ * HD_;

    const int qrow = qt*FBM + tid;
    const float scale = 0.125f;           // HD^-0.5

    float4 qreg[16];
    {
        const float4* qp = (const float4*)(Qb + (size_t)qrow * HD_);
        #pragma unroll
        for (int i = 0; i < 16; i++) {
            float4 t = qp[i];
            t.x *= scale; t.y *= scale; t.z *= scale; t.w *= scale;
            qreg[i] = t;
        }
    }

    float4 acc[16];
    #pragma unroll
    for (int i = 0; i < 16; i++) acc[i] = make_float4(0.f, 0.f, 0.f, 0.f);
    float mrow = -1e30f, lrow = 0.f;

    const int nkt = (qt + 1) * FBM / FBN;   // key tiles needed (causal)
    for (int kt = 0; kt < nkt; kt++) {
        const float4* kp = (const float4*)(Kb + (size_t)kt * FBN * HD_);
        const float4* vp = (const float4*)(Vb + (size_t)kt * FBN * HD_);
        float4* Ks4 = (float4*)Ks;
        float4* Vs4 = (float4*)Vs;
        #pragma unroll
        for (int it = 0; it < (FBN*HD_/4)/128; it++) {
            const int i = tid + it*128;
            Ks4[i] = kp[i];
            Vs4[i] = vp[i];
        }
        __syncthreads();

        // scores
        float tmax = -1e30f;
        #pragma unroll 4
        for (int j = 0; j < FBN; j++) {
            const float4* kr = (const float4*)(Ks + j*HD_);
            float s = 0.f;
            #pragma unroll
            for (int i = 0; i < 16; i++) {
                float4 kv = kr[i];
                s += qreg[i].x*kv.x + qreg[i].y*kv.y + qreg[i].z*kv.z + qreg[i].w*kv.w;
            }
            const int kg = kt*FBN + j;
            s = (kg <= qrow) ? s : -1e30f;
            Ss[tid*65 + j] = s;
            tmax = fmaxf(tmax, s);
        }

        const float mnew = fmaxf(mrow, tmax);
        const float corr = __expf(mrow - mnew);
        float psum = 0.f;
        #pragma unroll 4
        for (int j = 0; j < FBN; j++) {
            const float p = __expf(Ss[tid*65 + j] - mnew);
            Ss[tid*65 + j] = p;
            psum += p;
        }
        lrow = lrow * corr + psum;
        mrow = mnew;
        #pragma unroll
        for (int i = 0; i < 16; i++) {
            acc[i].x *= corr; acc[i].y *= corr; acc[i].z *= corr; acc[i].w *= corr;
        }
        #pragma unroll 2
        for (int j = 0; j < FBN; j++) {
            const float p = Ss[tid*65 + j];
            const float4* vr = (const float4*)(Vs + j*HD_);
            #pragma unroll
            for (int i = 0; i < 16; i++) {
                float4 vv = vr[i];
                acc[i].x += p*vv.x; acc[i].y += p*vv.y;
                acc[i].z += p*vv.z; acc[i].w += p*vv.w;
            }
        }
        __syncthreads();
    }

    const float inv = 1.f / lrow;
    float4* op = (float4*)(g_o + (((size_t)(b*L_ + qrow))*H_ + h) * HD_);
    #pragma unroll
    for (int i = 0; i < 16; i++) {
        float4 t = acc[i];
        t.x *= inv; t.y *= inv; t.z *= inv; t.w *= inv;
        op[i] = t;
    }
}

// ---------------- launch ----------------
extern "C" void kernel_launch(void* const* d_in, const int* in_sizes, int n_in,
                              void* d_out, int out_size)
{
    const float* hs = (const float*)d_in[0];
    const float* wq = (const float*)d_in[1];
    const float* bq = (const float*)d_in[2];
    const float* wk = (const float*)d_in[3];
    const float* bk = (const float*)d_in[4];
    const float* wv = (const float*)d_in[5];
    const float* bv = (const float*)d_in[6];
    const float* wo = (const float*)d_in[7];
    const float* bo = (const float*)d_in[8];
    float* out = (float*)d_out;

    const int smem_bytes = (2*FBN*HD_ + FBM*65) * (int)sizeof(float);  // 66048
    cudaFuncSetAttribute(flash_kernel, cudaFuncAttributeMaxDynamicSharedMemorySize, smem_bytes);

    qkv_gemm<<<dim3(DM_/BN, M_/BM, 3), 256>>>(hs, wq, bq, wk, bk, wv, bv);
    flash_kernel<<<dim3(L_/FBM, H_, B_), 128, smem_bytes>>>();
    out_gemm<<<dim3(DM_/BN, M_/BM, 1), 256>>>(wo, bo, out);
}

// round 2
// speedup vs baseline: 3.3939x; 3.3939x over previous
#include <cuda_runtime.h>
#include <math.h>
#include <stdint.h>

#define B_  4
#define L_  2048
#define H_  12
#define HD_ 64
#define DM_ 768
#define M_  (B_*L_)   // 8192

// Scratch (allocation-free rule: __device__ globals)
__device__ float g_q[B_*H_*L_*HD_];
__device__ float g_k[B_*H_*L_*HD_];
__device__ float g_v[B_*H_*L_*HD_];
__device__ float g_o[M_*DM_];

__device__ __forceinline__ float to_tf32(float x) {
    uint32_t o;
    asm("cvt.rna.tf32.f32 %0, %1;" : "=r"(o) : "f"(x));
    return __uint_as_float(o);
}

__device__ __forceinline__ void mma_tf32(float c[4], const uint32_t a[4], const uint32_t b[2]) {
    asm volatile(
        "mma.sync.aligned.m16n8k8.row.col.f32.tf32.tf32.f32 "
        "{%0,%1,%2,%3}, {%4,%5,%6,%7}, {%8,%9}, {%0,%1,%2,%3};\n"
        : "+f"(c[0]), "+f"(c[1]), "+f"(c[2]), "+f"(c[3])
        : "r"(a[0]), "r"(a[1]), "r"(a[2]), "r"(a[3]), "r"(b[0]), "r"(b[1]));
}

// =============== tf32 tensor-core GEMM: C[m,n] = sum_k A[m,k]*W[n,k] + bias[n] ===============
#define GBM 128
#define GBN 128
#define GBK 16
#define GPAD 20   // smem row stride (floats): conflict-free fragment LDS

template<bool SCATTER>
__device__ __forceinline__ void gemm_body(const float* __restrict__ A,
                                          const float* __restrict__ W,
                                          const float* __restrict__ bias,
                                          float* __restrict__ C)
{
    __shared__ float As[GBM][GPAD];
    __shared__ float Ws[GBN][GPAD];

    const int bm  = blockIdx.y * GBM;
    const int bn  = blockIdx.x * GBN;
    const int tid = threadIdx.x;          // 0..255
    const int wid = tid >> 5;
    const int lane = tid & 31;
    const int grp = lane >> 2;            // 0..7
    const int qid = lane & 3;             // 0..3

    const int wm = (wid & 3) * 32;        // warp m offset (4 warps along m)
    const int wn = (wid >> 2) * 64;       // warp n offset (2 warps along n)

    float acc[2][8][4];
    #pragma unroll
    for (int mi = 0; mi < 2; mi++)
        #pragma unroll
        for (int ni = 0; ni < 8; ni++)
            #pragma unroll
            for (int e = 0; e < 4; e++) acc[mi][ni][e] = 0.f;

    const int ldrow = tid >> 2;           // 0..63
    const int ldc4  = (tid & 3) * 4;      // 0,4,8,12

    for (int k0 = 0; k0 < DM_; k0 += GBK) {
        __syncthreads();
        // load A tile [128 x 16] and W tile [128 x 16]; 2 float4 each per thread
        #pragma unroll
        for (int h = 0; h < 2; h++) {
            const int r = ldrow + h*64;
            float4 av = *(const float4*)(A + (size_t)(bm + r) * DM_ + k0 + ldc4);
            float4 wv = *(const float4*)(W + (size_t)(bn + r) * DM_ + k0 + ldc4);
            av.x = to_tf32(av.x); av.y = to_tf32(av.y); av.z = to_tf32(av.z); av.w = to_tf32(av.w);
            wv.x = to_tf32(wv.x); wv.y = to_tf32(wv.y); wv.z = to_tf32(wv.z); wv.w = to_tf32(wv.w);
            *(float4*)&As[r][ldc4] = av;
            *(float4*)&Ws[r][ldc4] = wv;
        }
        __syncthreads();

        #pragma unroll
        for (int kk = 0; kk < GBK; kk += 8) {
            uint32_t a[2][4];
            #pragma unroll
            for (int mi = 0; mi < 2; mi++) {
                const int r = wm + mi*16;
                a[mi][0] = __float_as_uint(As[r + grp    ][kk + qid    ]);
                a[mi][1] = __float_as_uint(As[r + grp + 8][kk + qid    ]);
                a[mi][2] = __float_as_uint(As[r + grp    ][kk + qid + 4]);
                a[mi][3] = __float_as_uint(As[r + grp + 8][kk + qid + 4]);
            }
            uint32_t b[8][2];
            #pragma unroll
            for (int ni = 0; ni < 8; ni++) {
                b[ni][0] = __float_as_uint(Ws[wn + ni*8 + grp][kk + qid    ]);
                b[ni][1] = __float_as_uint(Ws[wn + ni*8 + grp][kk + qid + 4]);
            }
            #pragma unroll
            for (int mi = 0; mi < 2; mi++)
                #pragma unroll
                for (int ni = 0; ni < 8; ni++)
                    mma_tf32(acc[mi][ni], a[mi], b[ni]);
        }
    }

    // epilogue
    #pragma unroll
    for (int mi = 0; mi < 2; mi++) {
        #pragma unroll
        for (int half = 0; half < 2; half++) {
            const int m  = bm + wm + mi*16 + grp + half*8;
            const int bb = m / L_;
            const int l  = m % L_;
            #pragma unroll
            for (int ni = 0; ni < 8; ni++) {
                const int n = bn + wn + ni*8 + 2*qid;
                float v0 = acc[mi][ni][half*2 + 0] + bias[n];
                float v1 = acc[mi][ni][half*2 + 1] + bias[n + 1];
                if (SCATTER) {
                    const int h = n / HD_;
                    const int d = n % HD_;
                    float2* p = (float2*)&C[(((size_t)bb*H_ + h)*L_ + l)*HD_ + d];
                    *p = make_float2(v0, v1);
                } else {
                    float2* p = (float2*)&C[(size_t)m*DM_ + n];
                    *p = make_float2(v0, v1);
                }
            }
        }
    }
}

__global__ __launch_bounds__(256) void qkv_gemm(const float* __restrict__ X,
    const float* __restrict__ wq, const float* __restrict__ bq,
    const float* __restrict__ wk, const float* __restrict__ bk,
    const float* __restrict__ wv, const float* __restrict__ bv)
{
    const float* W; const float* bias; float* out;
    if (blockIdx.z == 0)      { W = wq; bias = bq; out = g_q; }
    else if (blockIdx.z == 1) { W = wk; bias = bk; out = g_k; }
    else                      { W = wv; bias = bv; out = g_v; }
    gemm_body<true>(X, W, bias, out);
}

__global__ __launch_bounds__(256) void out_gemm(const float* __restrict__ wo,
                                                const float* __restrict__ bo,
                                                float* __restrict__ out)
{
    gemm_body<false>(g_o, wo, bo, out);
}

// =============== causal flash attention, tf32 tensor cores ===============
// Q,K,V: [B,H,L,HD]; O written as [B,L,H,HD]
#define FBM 128
#define FBN 64
#define KS_STRIDE 68
#define VS_STRIDE 72
#define PS_STRIDE 68
#define FLASH_SMEM ((FBN*KS_STRIDE + FBN*VS_STRIDE + FBM*PS_STRIDE) * 4)

__global__ __launch_bounds__(256) void flash_kernel()
{
    extern __shared__ float sm[];
    float* Ks = sm;                               // [64][68]
    float* Vs = Ks + FBN*KS_STRIDE;               // [64][72]
    float* Ps = Vs + FBN*VS_STRIDE;               // [128][68]

    const int tid  = threadIdx.x;
    const int wid  = tid >> 5;                    // 0..7 (16 query rows each)
    const int lane = tid & 31;
    const int grp  = lane >> 2;
    const int qid  = lane & 3;

    const int qt = blockIdx.x;
    const int h  = blockIdx.y;
    const int b  = blockIdx.z;

    const float* Qb = g_q + (size_t)(b*H_ + h) * L_ * HD_;
    const float* Kb = g_k + (size_t)(b*H_ + h) * L_ * HD_;
    const float* Vb = g_v + (size_t)(b*H_ + h) * L_ * HD_;

    const int qrow0 = qt*FBM + wid*16;            // warp's first query row
    const float scale = 0.125f;

    // Q fragments: 8 k-chunks, resident for the whole kernel (pre-scaled, tf32)
    uint32_t qa[8][4];
    #pragma unroll
    for (int kc = 0; kc < 8; kc++) {
        qa[kc][0] = __float_as_uint(to_tf32(scale * Qb[(size_t)(qrow0 + grp    )*HD_ + kc*8 + qid    ]));
        qa[kc][1] = __float_as_uint(to_tf32(scale * Qb[(size_t)(qrow0 + grp + 8)*HD_ + kc*8 + qid    ]));
        qa[kc][2] = __float_as_uint(to_tf32(scale * Qb[(size_t)(qrow0 + grp    )*HD_ + kc*8 + qid + 4]));
        qa[kc][3] = __float_as_uint(to_tf32(scale * Qb[(size_t)(qrow0 + grp + 8)*HD_ + kc*8 + qid + 4]));
    }

    float o[8][4];
    #pragma unroll
    for (int ni = 0; ni < 8; ni++)
        #pragma unroll
        for (int e = 0; e < 4; e++) o[ni][e] = 0.f;
    float m0 = -1e30f, m1 = -1e30f, l0 = 0.f, l1 = 0.f;

    const int nkt = 2*(qt + 1);
    for (int kt = 0; kt < nkt; kt++) {
        __syncthreads();   // protect Ks/Vs from previous iteration readers
        // cooperative load of K,V tiles (64x64 each), tf32-converted
        #pragma unroll
        for (int it = 0; it < 4; it++) {
            const int id  = tid + it*256;
            const int row = id >> 4;
            const int c4  = (id & 15) * 4;
            float4 kv = *(const float4*)(Kb + (size_t)(kt*FBN + row)*HD_ + c4);
            float4 vv = *(const float4*)(Vb + (size_t)(kt*FBN + row)*HD_ + c4);
            kv.x = to_tf32(kv.x); kv.y = to_tf32(kv.y); kv.z = to_tf32(kv.z); kv.w = to_tf32(kv.w);
            vv.x = to_tf32(vv.x); vv.y = to_tf32(vv.y); vv.z = to_tf32(vv.z); vv.w = to_tf32(vv.w);
            *(float4*)&Ks[row*KS_STRIDE + c4] = kv;
            *(float4*)&Vs[row*VS_STRIDE + c4] = vv;
        }
        __syncthreads();

        // skip warps whose rows are entirely above this key tile (fully masked)
        if (kt*FBN > qrow0 + 15) continue;

        // ---- S = Q K^T (16 x 64 per warp) ----
        float sc[8][4];
        #pragma unroll
        for (int ni = 0; ni < 8; ni++)
            #pragma unroll
            for (int e = 0; e < 4; e++) sc[ni][e] = 0.f;

        #pragma unroll
        for (int kc = 0; kc < 8; kc++) {
            #pragma unroll
            for (int ni = 0; ni < 8; ni++) {
                uint32_t bfr[2];
                bfr[0] = __float_as_uint(Ks[(ni*8 + grp)*KS_STRIDE + kc*8 + qid    ]);
                bfr[1] = __float_as_uint(Ks[(ni*8 + grp)*KS_STRIDE + kc*8 + qid + 4]);
                mma_tf32(sc[ni], qa[kc], bfr);
            }
        }

        // causal mask (only tiles that touch the diagonal for this warp)
        if (kt*FBN + FBN - 1 > qrow0) {
            const int r0 = qrow0 + grp;
            const int r1 = r0 + 8;
            #pragma unroll
            for (int ni = 0; ni < 8; ni++) {
                const int kg = kt*FBN + ni*8 + 2*qid;
                if (kg     > r0) sc[ni][0] = -1e30f;
                if (kg + 1 > r0) sc[ni][1] = -1e30f;
                if (kg     > r1) sc[ni][2] = -1e30f;
                if (kg + 1 > r1) sc[ni][3] = -1e30f;
            }
        }

        // ---- online softmax ----
        float tm0 = -1e30f, tm1 = -1e30f;
        #pragma unroll
        for (int ni = 0; ni < 8; ni++) {
            tm0 = fmaxf(tm0, fmaxf(sc[ni][0], sc[ni][1]));
            tm1 = fmaxf(tm1, fmaxf(sc[ni][2], sc[ni][3]));
        }
        tm0 = fmaxf(tm0, __shfl_xor_sync(0xffffffff, tm0, 1));
        tm0 = fmaxf(tm0, __shfl_xor_sync(0xffffffff, tm0, 2));
        tm1 = fmaxf(tm1, __shfl_xor_sync(0xffffffff, tm1, 1));
        tm1 = fmaxf(tm1, __shfl_xor_sync(0xffffffff, tm1, 2));

        const float mn0 = fmaxf(m0, tm0);
        const float mn1 = fmaxf(m1, tm1);
        const float corr0 = __expf(m0 - mn0);
        const float corr1 = __expf(m1 - mn1);
        m0 = mn0; m1 = mn1;

        float ps0 = 0.f, ps1 = 0.f;
        #pragma unroll
        for (int ni = 0; ni < 8; ni++) {
            sc[ni][0] = __expf(sc[ni][0] - mn0);
            sc[ni][1] = __expf(sc[ni][1] - mn0);
            sc[ni][2] = __expf(sc[ni][2] - mn1);
            sc[ni][3] = __expf(sc[ni][3] - mn1);
            ps0 += sc[ni][0] + sc[ni][1];
            ps1 += sc[ni][2] + sc[ni][3];
        }
        ps0 += __shfl_xor_sync(0xffffffff, ps0, 1);
        ps0 += __shfl_xor_sync(0xffffffff, ps0, 2);
        ps1 += __shfl_xor_sync(0xffffffff, ps1, 1);
        ps1 += __shfl_xor_sync(0xffffffff, ps1, 2);
        l0 = l0*corr0 + ps0;
        l1 = l1*corr1 + ps1;

        #pragma unroll
        for (int ni = 0; ni < 8; ni++) {
            o[ni][0] *= corr0; o[ni][1] *= corr0;
            o[ni][2] *= corr1; o[ni][3] *= corr1;
        }

        // ---- write P to per-warp-private smem (tf32) ----
        const int prow = wid*16 + grp;
        #pragma unroll
        for (int ni = 0; ni < 8; ni++) {
            *(float2*)&Ps[(prow    )*PS_STRIDE + ni*8 + 2*qid] =
                make_float2(to_tf32(sc[ni][0]), to_tf32(sc[ni][1]));
            *(float2*)&Ps[(prow + 8)*PS_STRIDE + ni*8 + 2*qid] =
                make_float2(to_tf32(sc[ni][2]), to_tf32(sc[ni][3]));
        }
        __syncwarp();

        // ---- O += P V ----
        #pragma unroll
        for (int kc = 0; kc < 8; kc++) {
            uint32_t pa[4];
            pa[0] = __float_as_uint(Ps[(wid*16 + grp    )*PS_STRIDE + kc*8 + qid    ]);
            pa[1] = __float_as_uint(Ps[(wid*16 + grp + 8)*PS_STRIDE + kc*8 + qid    ]);
            pa[2] = __float_as_uint(Ps[(wid*16 + grp    )*PS_STRIDE + kc*8 + qid + 4]);
            pa[3] = __float_as_uint(Ps[(wid*16 + grp + 8)*PS_STRIDE + kc*8 + qid + 4]);
            #pragma unroll
            for (int ni = 0; ni < 8; ni++) {
                uint32_t bfr[2];
                bfr[0] = __float_as_uint(Vs[(kc*8 + qid    )*VS_STRIDE + ni*8 + grp]);
                bfr[1] = __float_as_uint(Vs[(kc*8 + qid + 4)*VS_STRIDE + ni*8 + grp]);
                mma_tf32(o[ni], pa, bfr);
            }
        }
    }

    // ---- normalize + store O as [B, L, H, HD] ----
    const float inv0 = 1.f / l0;
    const float inv1 = 1.f / l1;
    const int r0 = qrow0 + grp;
    const int r1 = r0 + 8;
    float* O0 = g_o + (((size_t)(b*L_ + r0))*H_ + h) * HD_;
    float* O1 = g_o + (((size_t)(b*L_ + r1))*H_ + h) * HD_;
    #pragma unroll
    for (int ni = 0; ni < 8; ni++) {
        const int col = ni*8 + 2*qid;
        *(float2*)&O0[col] = make_float2(o[ni][0]*inv0, o[ni][1]*inv0);
        *(float2*)&O1[col] = make_float2(o[ni][2]*inv1, o[ni][3]*inv1);
    }
}

// =============== launch ===============
extern "C" void kernel_launch(void* const* d_in, const int* in_sizes, int n_in,
                              void* d_out, int out_size)
{
    const float* hs = (const float*)d_in[0];
    const float* wq = (const float*)d_in[1];
    const float* bq = (const float*)d_in[2];
    const float* wk = (const float*)d_in[3];
    const float* bk = (const float*)d_in[4];
    const float* wv = (const float*)d_in[5];
    const float* bv = (const float*)d_in[6];
    const float* wo = (const float*)d_in[7];
    const float* bo = (const float*)d_in[8];
    float* out = (float*)d_out;

    cudaFuncSetAttribute(flash_kernel, cudaFuncAttributeMaxDynamicSharedMemorySize, FLASH_SMEM);

    qkv_gemm<<<dim3(DM_/GBN, M_/GBM, 3), 256>>>(hs, wq, bq, wk, bk, wv, bv);
    flash_kernel<<<dim3(L_/FBM, H_, B_), 256, FLASH_SMEM>>>();
    out_gemm<<<dim3(DM_/GBN, M_/GBM, 1), 256>>>(wo, bo, out);
}

// round 3
// speedup vs baseline: 3.9773x; 1.1719x over previous
#include <cuda_runtime.h>
#include <math.h>
#include <stdint.h>

#define B_  4
#define L_  2048
#define H_  12
#define HD_ 64
#define DM_ 768
#define M_  (B_*L_)   // 8192

__device__ float g_q[B_*H_*L_*HD_];
__device__ float g_k[B_*H_*L_*HD_];
__device__ float g_v[B_*H_*L_*HD_];
__device__ float g_o[M_*DM_];

__device__ __forceinline__ float to_tf32(float x) {
    uint32_t o;
    asm("cvt.rna.tf32.f32 %0, %1;" : "=r"(o) : "f"(x));
    return __uint_as_float(o);
}
__device__ __forceinline__ uint32_t tf32b(float x) {
    uint32_t o;
    asm("cvt.rna.tf32.f32 %0, %1;" : "=r"(o) : "f"(x));
    return o;
}
__device__ __forceinline__ void mma_tf32(float c[4], const uint32_t a[4], const uint32_t b[2]) {
    asm volatile(
        "mma.sync.aligned.m16n8k8.row.col.f32.tf32.tf32.f32 "
        "{%0,%1,%2,%3}, {%4,%5,%6,%7}, {%8,%9}, {%0,%1,%2,%3};\n"
        : "+f"(c[0]), "+f"(c[1]), "+f"(c[2]), "+f"(c[3])
        : "r"(a[0]), "r"(a[1]), "r"(a[2]), "r"(a[3]), "r"(b[0]), "r"(b[1]));
}
__device__ __forceinline__ void cp_async16(uint32_t saddr, const void* gptr) {
    asm volatile("cp.async.ca.shared.global [%0], [%1], 16;\n" :: "r"(saddr), "l"(gptr));
}
__device__ __forceinline__ void cp_commit() {
    asm volatile("cp.async.commit_group;\n");
}
__device__ __forceinline__ void cp_wait_all() {
    asm volatile("cp.async.wait_group 0;\n");
}

// ============ GEMM: C[m,n] = sum_k A[m,k]*W[n,k] + bias[n] ============
// 128 threads, 4 warps (2m x 2n), 64x64 warp tiles, block 128x128, GBK=16
#define GBK  16
#define GPAD 20

template<bool SCATTER>
__device__ __forceinline__ void gemm_body(const float* __restrict__ A,
                                          const float* __restrict__ W,
                                          const float* __restrict__ bias,
                                          float* __restrict__ C)
{
    __shared__ float As[2][128*GPAD];
    __shared__ float Ws[2][128*GPAD];

    const int bm  = blockIdx.y * 128;
    const int bn  = blockIdx.x * 128;
    const int tid = threadIdx.x;          // 0..127
    const int wid = tid >> 5;
    const int lane = tid & 31;
    const int grp = lane >> 2;
    const int qid = lane & 3;
    const int wm = (wid & 1) * 64;
    const int wn = (wid >> 1) * 64;

    float acc[4][8][4];
    #pragma unroll
    for (int mi = 0; mi < 4; mi++)
        #pragma unroll
        for (int ni = 0; ni < 8; ni++)
            #pragma unroll
            for (int e = 0; e < 4; e++) acc[mi][ni][e] = 0.f;

    const int lr = tid >> 2;              // 0..31
    const int c4 = (tid & 3) * 4;         // 0,4,8,12

    // prologue load (buffer 0)
    {
        #pragma unroll
        for (int hh = 0; hh < 4; hh++) {
            const int row = lr + hh*32;
            uint32_t sa = (uint32_t)__cvta_generic_to_shared(&As[0][row*GPAD + c4]);
            uint32_t sw = (uint32_t)__cvta_generic_to_shared(&Ws[0][row*GPAD + c4]);
            cp_async16(sa, A + (size_t)(bm + row)*DM_ + c4);
            cp_async16(sw, W + (size_t)(bn + row)*DM_ + c4);
        }
        cp_commit();
    }

    int cur = 0;
    for (int k0 = 0; k0 < DM_; k0 += GBK) {
        cp_wait_all();
        __syncthreads();

        // prefetch next tile into the other buffer
        if (k0 + GBK < DM_) {
            const int nxt = cur ^ 1;
            #pragma unroll
            for (int hh = 0; hh < 4; hh++) {
                const int row = lr + hh*32;
                uint32_t sa = (uint32_t)__cvta_generic_to_shared(&As[nxt][row*GPAD + c4]);
                uint32_t sw = (uint32_t)__cvta_generic_to_shared(&Ws[nxt][row*GPAD + c4]);
                cp_async16(sa, A + (size_t)(bm + row)*DM_ + k0 + GBK + c4);
                cp_async16(sw, W + (size_t)(bn + row)*DM_ + k0 + GBK + c4);
            }
            cp_commit();
        }

        #pragma unroll
        for (int kb = 0; kb < 2; kb++) {
            const int kk = kb*8;
            uint32_t af[4][4];
            #pragma unroll
            for (int mi = 0; mi < 4; mi++) {
                const int r0 = wm + mi*16 + grp;
                af[mi][0] = tf32b(As[cur][(r0    )*GPAD + kk + qid    ]);
                af[mi][1] = tf32b(As[cur][(r0 + 8)*GPAD + kk + qid    ]);
                af[mi][2] = tf32b(As[cur][(r0    )*GPAD + kk + qid + 4]);
                af[mi][3] = tf32b(As[cur][(r0 + 8)*GPAD + kk + qid + 4]);
            }
            #pragma unroll
            for (int ni = 0; ni < 8; ni++) {
                uint32_t bf[2];
                const int rn = wn + ni*8 + grp;
                bf[0] = tf32b(Ws[cur][rn*GPAD + kk + qid    ]);
                bf[1] = tf32b(Ws[cur][rn*GPAD + kk + qid + 4]);
                #pragma unroll
                for (int mi = 0; mi < 4; mi++)
                    mma_tf32(acc[mi][ni], af[mi], bf);
            }
        }
        cur ^= 1;
        __syncthreads();
    }

    #pragma unroll
    for (int mi = 0; mi < 4; mi++) {
        #pragma unroll
        for (int half = 0; half < 2; half++) {
            const int m  = bm + wm + mi*16 + grp + half*8;
            const int bb = m / L_;
            const int l  = m % L_;
            #pragma unroll
            for (int ni = 0; ni < 8; ni++) {
                const int n = bn + wn + ni*8 + 2*qid;
                float v0 = acc[mi][ni][half*2 + 0] + bias[n];
                float v1 = acc[mi][ni][half*2 + 1] + bias[n + 1];
                if (SCATTER) {
                    const int hh = n / HD_;
                    const int d  = n % HD_;
                    *(float2*)&C[(((size_t)bb*H_ + hh)*L_ + l)*HD_ + d] = make_float2(v0, v1);
                } else {
                    *(float2*)&C[(size_t)m*DM_ + n] = make_float2(v0, v1);
                }
            }
        }
    }
}

__global__ __launch_bounds__(128, 3) void qkv_gemm(const float* __restrict__ X,
    const float* __restrict__ wq, const float* __restrict__ bq,
    const float* __restrict__ wk, const float* __restrict__ bk,
    const float* __restrict__ wv, const float* __restrict__ bv)
{
    const float* W; const float* bias; float* out;
    if (blockIdx.z == 0)      { W = wq; bias = bq; out = g_q; }
    else if (blockIdx.z == 1) { W = wk; bias = bk; out = g_k; }
    else                      { W = wv; bias = bv; out = g_v; }
    gemm_body<true>(X, W, bias, out);
}

__global__ __launch_bounds__(128, 3) void out_gemm(const float* __restrict__ wo,
                                                   const float* __restrict__ bo,
                                                   float* __restrict__ out)
{
    gemm_body<false>(g_o, wo, bo, out);
}

// ============ causal flash attention (tf32 mma, shfl P-exchange) ============
// Q,K,V: [B,H,L,HD]; O: [B,L,H,HD]. FQ=64 rows/CTA, 4 warps x 16 rows.
#define FQ  64
#define KSK 88     // K row stride (floats), 88 % 32 == 24 -> conflict-free
#define VSV 136    // V pair-row stride,     136 % 32 == 8 -> conflict-free

__global__ __launch_bounds__(128, 3) void flash_kernel()
{
    __shared__ float Ks[64*KSK];
    __shared__ float Vp[32*VSV];

    const int tid  = threadIdx.x;
    const int wid  = tid >> 5;
    const int lane = tid & 31;
    const int grp  = lane >> 2;
    const int qid  = lane & 3;

    const int qt = (int)gridDim.x - 1 - (int)blockIdx.x;  // descending work
    const int h  = blockIdx.y % H_;
    const int b  = blockIdx.y / H_;

    const float* Qb = g_q + (size_t)(b*H_ + h) * L_ * HD_;
    const float* Kb = g_k + (size_t)(b*H_ + h) * L_ * HD_;
    const float* Vb = g_v + (size_t)(b*H_ + h) * L_ * HD_;

    const int qrow0 = qt*FQ + wid*16;
    const float scale = 0.125f;

    uint32_t qa[8][4];
    #pragma unroll
    for (int kc = 0; kc < 8; kc++) {
        qa[kc][0] = tf32b(scale * Qb[(size_t)(qrow0 + grp    )*HD_ + kc*8 + qid    ]);
        qa[kc][1] = tf32b(scale * Qb[(size_t)(qrow0 + grp + 8)*HD_ + kc*8 + qid    ]);
        qa[kc][2] = tf32b(scale * Qb[(size_t)(qrow0 + grp    )*HD_ + kc*8 + qid + 4]);
        qa[kc][3] = tf32b(scale * Qb[(size_t)(qrow0 + grp + 8)*HD_ + kc*8 + qid + 4]);
    }

    float o[8][4];
    #pragma unroll
    for (int ni = 0; ni < 8; ni++)
        #pragma unroll
        for (int e = 0; e < 4; e++) o[ni][e] = 0.f;
    float m0 = -1e30f, m1 = -1e30f, l0 = 0.f, l1 = 0.f;

    for (int kt = 0; kt <= qt; kt++) {
        __syncthreads();
        // load K,V tile (64x64 each) into paired layouts, tf32-rounded
        #pragma unroll
        for (int it = 0; it < 8; it++) {
            const int id  = tid + it*128;
            const int row = id >> 4;
            const int c4  = (id & 15) * 4;
            float4 kv = *(const float4*)(Kb + (size_t)(kt*FQ + row)*HD_ + c4);
            float4 vv = *(const float4*)(Vb + (size_t)(kt*FQ + row)*HD_ + c4);
            // K: element k -> (k>>3)*8 + (k&3)*2 + ((k>>2)&1)
            const int kbase = row*KSK + ((c4>>3)<<3) + ((c4>>2)&1);
            Ks[kbase + 0] = to_tf32(kv.x);
            Ks[kbase + 2] = to_tf32(kv.y);
            Ks[kbase + 4] = to_tf32(kv.z);
            Ks[kbase + 6] = to_tf32(kv.w);
            // V: pair rows (j, j+4): p = (j>>3)*4 + (j&3), slot = (j>>2)&1
            const int p = ((row>>3)<<2) + (row&3);
            const int slot = (row>>2) & 1;
            const int vbase = p*VSV + slot;
            const int x = c4 >> 4;  // swizzle: col' = col ^ (col>>4)
            Vp[vbase + (((c4+0)^x)<<1)] = to_tf32(vv.x);
            Vp[vbase + (((c4+1)^x)<<1)] = to_tf32(vv.y);
            Vp[vbase + (((c4+2)^x)<<1)] = to_tf32(vv.z);
            Vp[vbase + (((c4+3)^x)<<1)] = to_tf32(vv.w);
        }
        __syncthreads();

        // ---- S = Q K^T ----
        float sc[8][4];
        #pragma unroll
        for (int ni = 0; ni < 8; ni++)
            #pragma unroll
            for (int e = 0; e < 4; e++) sc[ni][e] = 0.f;

        #pragma unroll
        for (int kc = 0; kc < 8; kc++) {
            #pragma unroll
            for (int ni = 0; ni < 8; ni++) {
                float2 kf = *(const float2*)&Ks[(ni*8 + grp)*KSK + kc*8 + qid*2];
                uint32_t bfr[2] = { __float_as_uint(kf.x), __float_as_uint(kf.y) };
                mma_tf32(sc[ni], qa[kc], bfr);
            }
        }

        // causal mask only on the diagonal tile
        if (kt == qt) {
            const int r0 = qrow0 + grp;
            const int r1 = r0 + 8;
            #pragma unroll
            for (int ni = 0; ni < 8; ni++) {
                const int kg = kt*FQ + ni*8 + 2*qid;
                if (kg     > r0) sc[ni][0] = -1e30f;
                if (kg + 1 > r0) sc[ni][1] = -1e30f;
                if (kg     > r1) sc[ni][2] = -1e30f;
                if (kg + 1 > r1) sc[ni][3] = -1e30f;
            }
        }

        // ---- online softmax ----
        float tm0 = -1e30f, tm1 = -1e30f;
        #pragma unroll
        for (int ni = 0; ni < 8; ni++) {
            tm0 = fmaxf(tm0, fmaxf(sc[ni][0], sc[ni][1]));
            tm1 = fmaxf(tm1, fmaxf(sc[ni][2], sc[ni][3]));
        }
        tm0 = fmaxf(tm0, __shfl_xor_sync(0xffffffffu, tm0, 1));
        tm0 = fmaxf(tm0, __shfl_xor_sync(0xffffffffu, tm0, 2));
        tm1 = fmaxf(tm1, __shfl_xor_sync(0xffffffffu, tm1, 1));
        tm1 = fmaxf(tm1, __shfl_xor_sync(0xffffffffu, tm1, 2));

        const float mn0 = fmaxf(m0, tm0);
        const float mn1 = fmaxf(m1, tm1);
        const float corr0 = __expf(m0 - mn0);
        const float corr1 = __expf(m1 - mn1);
        m0 = mn0; m1 = mn1;

        float ps0 = 0.f, ps1 = 0.f;
        #pragma unroll
        for (int ni = 0; ni < 8; ni++) {
            sc[ni][0] = to_tf32(__expf(sc[ni][0] - mn0));
            sc[ni][1] = to_tf32(__expf(sc[ni][1] - mn0));
            sc[ni][2] = to_tf32(__expf(sc[ni][2] - mn1));
            sc[ni][3] = to_tf32(__expf(sc[ni][3] - mn1));
            ps0 += sc[ni][0] + sc[ni][1];
            ps1 += sc[ni][2] + sc[ni][3];
        }
        ps0 += __shfl_xor_sync(0xffffffffu, ps0, 1);
        ps0 += __shfl_xor_sync(0xffffffffu, ps0, 2);
        ps1 += __shfl_xor_sync(0xffffffffu, ps1, 1);
        ps1 += __shfl_xor_sync(0xffffffffu, ps1, 2);
        l0 = l0*corr0 + ps0;
        l1 = l1*corr1 + ps1;

        #pragma unroll
        for (int ni = 0; ni < 8; ni++) {
            o[ni][0] *= corr0; o[ni][1] *= corr0;
            o[ni][2] *= corr1; o[ni][3] *= corr1;
        }

        // ---- O += P V (P via shuffle: c-layout -> a-layout) ----
        const int sA = (lane & ~3) | (qid >> 1);
        const bool hiq = (qid & 1);
        #pragma unroll
        for (int kc = 0; kc < 8; kc++) {
            float e0A = __shfl_sync(0xffffffffu, sc[kc][0], sA);
            float e1A = __shfl_sync(0xffffffffu, sc[kc][1], sA);
            float e2A = __shfl_sync(0xffffffffu, sc[kc][2], sA);
            float e3A = __shfl_sync(0xffffffffu, sc[kc][3], sA);
            float e0B = __shfl_sync(0xffffffffu, sc[kc][0], sA + 2);
            float e1B = __shfl_sync(0xffffffffu, sc[kc][1], sA + 2);
            float e2B = __shfl_sync(0xffffffffu, sc[kc][2], sA + 2);
            float e3B = __shfl_sync(0xffffffffu, sc[kc][3], sA + 2);
            uint32_t pa[4];
            pa[0] = __float_as_uint(hiq ? e1A : e0A);
            pa[1] = __float_as_uint(hiq ? e3A : e2A);
            pa[2] = __float_as_uint(hiq ? e1B : e0B);
            pa[3] = __float_as_uint(hiq ? e3B : e2B);
            #pragma unroll
            for (int ni = 0; ni < 8; ni++) {
                float2 vf = *(const float2*)&Vp[(kc*4 + qid)*VSV + (((ni*8 + grp) ^ (ni>>1))<<1)];
                uint32_t bfr[2] = { __float_as_uint(vf.x), __float_as_uint(vf.y) };
                mma_tf32(o[ni], pa, bfr);
            }
        }
    }

    // ---- normalize + store O as [B, L, H, HD] ----
    const float inv0 = 1.f / l0;
    const float inv1 = 1.f / l1;
    const int r0 = qrow0 + grp;
    const int r1 = r0 + 8;
    float* O0 = g_o + (((size_t)(b*L_ + r0))*H_ + h) * HD_;
    float* O1 = g_o + (((size_t)(b*L_ + r1))*H_ + h) * HD_;
    #pragma unroll
    for (int ni = 0; ni < 8; ni++) {
        const int col = ni*8 + 2*qid;
        *(float2*)&O0[col] = make_float2(o[ni][0]*inv0, o[ni][1]*inv0);
        *(float2*)&O1[col] = make_float2(o[ni][2]*inv1, o[ni][3]*inv1);
    }
}

// ============ launch ============
extern "C" void kernel_launch(void* const* d_in, const int* in_sizes, int n_in,
                              void* d_out, int out_size)
{
    const float* hs = (const float*)d_in[0];
    const float* wq = (const float*)d_in[1];
    const float* bq = (const float*)d_in[2];
    const float* wk = (const float*)d_in[3];
    const float* bk = (const float*)d_in[4];
    const float* wv = (const float*)d_in[5];
    const float* bv = (const float*)d_in[6];
    const float* wo = (const float*)d_in[7];
    const float* bo = (const float*)d_in[8];
    float* out = (float*)d_out;

    qkv_gemm<<<dim3(DM_/128, M_/128, 3), 128>>>(hs, wq, bq, wk, bk, wv, bv);
    flash_kernel<<<dim3(L_/FQ, H_*B_), 128>>>();
    out_gemm<<<dim3(DM_/128, M_/128), 128>>>(wo, bo, out);
}